// round 4
// baseline (speedup 1.0000x reference)
#include <cuda_runtime.h>
#include <cfloat>

#define B   32
#define C   512
#define H   56
#define W   56
#define HW  (H * W)          // 3136
#define HW4 (HW / 4)         // 784
#define KD  768

#define GROUPB 8             // batches per group (8 * 6.4MB = 51MB, L2-resident)
#define NGROUP (B / GROUPB)  // 4

// pooling block geometry: 16 hw4-columns x 16 channel-chunks
#define PTX 16
#define PTY 16
#define PCC (C / PTY)        // 32 channels per chunk
#define PBLK_PER_B (HW4 / PTX)   // 49

// conv tiling
#define CROWS 4
#define CTH   (CROWS + 6)
#define CTW   64

// Scratch (alloc-free rule: __device__ globals)
__device__ float g_pooled[B * 2 * HW];
__device__ float g_scale[B * HW];
__device__ float g_bias[B];

// ---------------------------------------------------------------------------
// Kernel 1: fused channel max+mean pooling for one batch group.
// Default-cached loads so x[group] stays L2-resident for mul.
// ---------------------------------------------------------------------------
__global__ void pool_kernel(const float4* __restrict__ x4, int b0) {
    int tx = threadIdx.x & (PTX - 1);
    int ty = threadIdx.x >> 4;
    int b   = b0 + blockIdx.y;
    int hw4 = blockIdx.x * PTX + tx;

    const float4* p = x4 + (size_t)b * C * HW4
                         + (size_t)ty * PCC * HW4 + hw4;
    float4 v0 = __ldg(p);
    float4 mx = v0;
    float4 sm = v0;
#pragma unroll
    for (int c = 1; c < PCC; ++c) {
        float4 v = __ldg(p + (size_t)c * HW4);
        mx.x = fmaxf(mx.x, v.x); mx.y = fmaxf(mx.y, v.y);
        mx.z = fmaxf(mx.z, v.z); mx.w = fmaxf(mx.w, v.w);
        sm.x += v.x; sm.y += v.y; sm.z += v.z; sm.w += v.w;
    }

    __shared__ float4 smax[PTY][PTX];
    __shared__ float4 ssum[PTY][PTX];
    smax[ty][tx] = mx;
    ssum[ty][tx] = sm;
    __syncthreads();

#pragma unroll
    for (int s = PTY / 2; s > 0; s >>= 1) {
        if (ty < s) {
            float4 m = smax[ty + s][tx];
            float4 q = ssum[ty + s][tx];
            mx.x = fmaxf(mx.x, m.x); mx.y = fmaxf(mx.y, m.y);
            mx.z = fmaxf(mx.z, m.z); mx.w = fmaxf(mx.w, m.w);
            sm.x += q.x; sm.y += q.y; sm.z += q.z; sm.w += q.w;
            smax[ty][tx] = mx;
            ssum[ty][tx] = sm;
        }
        __syncthreads();
    }

    if (ty == 0) {
        const float inv = 1.0f / C;
        sm.x *= inv; sm.y *= inv; sm.z *= inv; sm.w *= inv;
        float4* pool4 = reinterpret_cast<float4*>(g_pooled);
        pool4[(b * 2 * HW) / 4 + hw4]      = mx;
        pool4[(b * 2 * HW + HW) / 4 + hw4] = sm;
    }
}

// ---------------------------------------------------------------------------
// Kernel 2: keyword bias. One block per batch.
// ---------------------------------------------------------------------------
__global__ void bias_kernel(const float* __restrict__ keyword,
                            const float* __restrict__ proj_w,
                            const float* __restrict__ proj_b) {
    int b = blockIdx.x;
    int tid = threadIdx.x;
    float s = 0.0f;
    for (int k = tid; k < KD; k += blockDim.x)
        s += keyword[b * KD + k] * proj_w[k];
#pragma unroll
    for (int off = 16; off > 0; off >>= 1)
        s += __shfl_down_sync(0xFFFFFFFFu, s, off);
    __shared__ float smem[8];
    if ((tid & 31) == 0) smem[tid >> 5] = s;
    __syncthreads();
    if (tid == 0) {
        float t = 0.0f;
        int nw = blockDim.x >> 5;
        for (int i = 0; i < nw; ++i) t += smem[i];
        g_bias[b] = t + proj_b[0];
    }
}

// ---------------------------------------------------------------------------
// Kernel 3: smem-tiled 7x7 conv + biases + sigmoid for one batch group.
// ---------------------------------------------------------------------------
__global__ void conv_kernel(const float* __restrict__ conv_w,
                            const float* __restrict__ conv_b, int b0) {
    __shared__ float tile[2][CTH][CTW];
    __shared__ float wts[98];
    __shared__ float sbias;

    int b  = b0 + blockIdx.y;
    int r0 = blockIdx.x * CROWS;
    int tid = threadIdx.x;

    if (tid < 98) wts[tid] = conv_w[tid];
    if (tid == 0) sbias = conv_b[0] + g_bias[b];

    const float* pb = g_pooled + b * 2 * HW;
    for (int i = tid; i < 2 * CTH * CTW; i += blockDim.x) {
        int ci = i / (CTH * CTW);
        int rr = (i / CTW) % CTH;
        int cc = i % CTW;
        int hh = r0 + rr - 3;
        int ww = cc - 3;
        float v = 0.0f;
        if ((unsigned)hh < (unsigned)H && (unsigned)ww < (unsigned)W)
            v = pb[ci * HW + hh * W + ww];
        tile[ci][rr][cc] = v;
    }
    __syncthreads();

    if (tid < CROWS * W) {
        int r = tid / W;
        int w = tid - r * W;
        float acc = sbias;
#pragma unroll
        for (int ci = 0; ci < 2; ++ci) {
#pragma unroll
            for (int kh = 0; kh < 7; ++kh) {
#pragma unroll
                for (int kw = 0; kw < 7; ++kw) {
                    acc += tile[ci][r + kh][w + kw] * wts[ci * 49 + kh * 7 + kw];
                }
            }
        }
        g_scale[b * HW + (r0 + r) * W + w] = 1.0f / (1.0f + __expf(-acc));
    }
}

// ---------------------------------------------------------------------------
// Kernel 4: out = x * scale for one batch group. x should be L2-resident
// (loaded by pool two launches ago). __ldcs: consume-and-evict.
// ---------------------------------------------------------------------------
__global__ void mul_kernel(const float4* __restrict__ x4,
                           float4* __restrict__ out4, int b0) {
    const int CHW4 = C * HW4;
    const int NG4  = GROUPB * CHW4;       // float4s per group
    int i = blockIdx.x * blockDim.x + threadIdx.x;
    if (i >= NG4) return;
    int bl  = i / CHW4;                   // batch within group
    int rem = i - bl * CHW4;
    int hw4 = rem % HW4;
    int b   = b0 + bl;

    size_t gi = (size_t)b * CHW4 + rem;
    float4 s = reinterpret_cast<const float4*>(g_scale)[b * HW4 + hw4];
    float4 v = __ldcs(x4 + gi);
    v.x *= s.x; v.y *= s.y; v.z *= s.z; v.w *= s.w;
    __stcs(out4 + gi, v);
}

// ---------------------------------------------------------------------------
extern "C" void kernel_launch(void* const* d_in, const int* in_sizes, int n_in,
                              void* d_out, int out_size) {
    const float* x       = (const float*)d_in[0];
    const float* keyword = (const float*)d_in[1];
    const float* conv_w  = (const float*)d_in[2];
    const float* conv_b  = (const float*)d_in[3];
    const float* proj_w  = (const float*)d_in[4];
    const float* proj_b  = (const float*)d_in[5];
    float* out = (float*)d_out;

    bias_kernel<<<B, 256>>>(keyword, proj_w, proj_b);

    const int NG4 = GROUPB * C * HW4;     // float4s per group
    for (int g = 0; g < NGROUP; ++g) {
        int b0 = g * GROUPB;
        {
            dim3 grid(PBLK_PER_B, GROUPB);    // 49 x 8
            pool_kernel<<<grid, PTX * PTY>>>((const float4*)x, b0);
        }
        {
            dim3 grid(H / CROWS, GROUPB);     // 14 x 8
            conv_kernel<<<grid, 256>>>(conv_w, conv_b, b0);
        }
        mul_kernel<<<(NG4 + 255) / 256, 256>>>((const float4*)x, (float4*)out, b0);
    }
}